// round 6
// baseline (speedup 1.0000x reference)
#include <cuda_runtime.h>
#include <cuda_bf16.h>

// QuantumKernelRegressor: X[2048,64], support[1024,64], W[1,1024], b[1] -> out[2048]
// out[i] = sum_j W[j] * prod_f cos^2((X[i,f]-S[j,f])/2) + b
// Identity: cos^2((x-s)/2) = 0.5 + (0.5 cos x)(cos s) + (0.5 sin x)(sin s)
#define BB 2048
#define SS 1024
#define FF 64

#define BI 64          // i-rows per block
#define BJ 256         // j-cols per block
#define TI 8           // i per thread: i_local = ty + ii*8
#define TJP 4          // j-pairs per thread: pair = tx + jp*32, j = 2*pair
#define NTHREADS 256   // 32 lanes (j-pairs) x 8 warps (i)
#define NSPLIT (SS / BJ)   // 4 j-splits
// grid = (2048/64, 4) = 128 blocks <= 148 SMs -> single wave, no quantization

typedef unsigned long long u64;

// __device__ scratch (allocation-free rule)
__device__ float2 g_Xc[BB * FF];   // splat (0.5cos x, 0.5cos x), [i][f]
__device__ float2 g_Xs[BB * FF];   // splat (0.5sin x, 0.5sin x), [i][f]
__device__ float  g_Sc[FF * SS];   // cos(s) plane, [f][j] (transposed)
__device__ float  g_Ss[FF * SS];   // sin(s) plane, [f][j]
__device__ float  g_partial[NSPLIT * BB];

// ---- packed f32x2 helpers (FFMA2/FMUL2 reachable only via PTX) ----
__device__ __forceinline__ u64 fma2(u64 a, u64 b, u64 c) {
    u64 d;
    asm("fma.rn.f32x2 %0, %1, %2, %3;" : "=l"(d) : "l"(a), "l"(b), "l"(c));
    return d;
}
__device__ __forceinline__ u64 mul2(u64 a, u64 b) {
    u64 d;
    asm("mul.rn.f32x2 %0, %1, %2;" : "=l"(d) : "l"(a), "l"(b));
    return d;
}
#define HALF2 0x3F0000003F000000ULL   // packed (0.5f, 0.5f)
#define ONE2  0x3F8000003F800000ULL   // packed (1.0f, 1.0f)

#define NX4 (BB * FF / 4)   // 32768 float4 work-items for X
#define NS4 (SS * FF / 4)   // 16384 float4 work-items for support

// ---------------------------------------------------------------------------
// Phase 1: fused sincos tables, fully float4-vectorized (one launch).
//   e <  NX4 : X part  -> splatted (0.5cos, 0.5cos)/(0.5sin, 0.5sin) tables
//   e >= NX4 : S part  -> planar transposed cos/sin tables [f][j]
// ---------------------------------------------------------------------------
__global__ void prep_kernel(const float* __restrict__ X, const float* __restrict__ Sup) {
    int e = blockIdx.x * blockDim.x + threadIdx.x;
    if (e < NX4) {
        float4 x = ((const float4*)X)[e];
        float s0, c0, s1, c1, s2, c2, s3, c3;
        sincosf(x.x, &s0, &c0);
        sincosf(x.y, &s1, &c1);
        sincosf(x.z, &s2, &c2);
        sincosf(x.w, &s3, &c3);
        float2* pc = g_Xc + e * 4;
        float2* ps = g_Xs + e * 4;
        pc[0] = make_float2(0.5f * c0, 0.5f * c0);
        pc[1] = make_float2(0.5f * c1, 0.5f * c1);
        pc[2] = make_float2(0.5f * c2, 0.5f * c2);
        pc[3] = make_float2(0.5f * c3, 0.5f * c3);
        ps[0] = make_float2(0.5f * s0, 0.5f * s0);
        ps[1] = make_float2(0.5f * s1, 0.5f * s1);
        ps[2] = make_float2(0.5f * s2, 0.5f * s2);
        ps[3] = make_float2(0.5f * s3, 0.5f * s3);
    } else if (e < NX4 + NS4) {
        int k  = (e - NX4) * 4;        // 4 consecutive f's of the same j (FF % 4 == 0)
        int j  = k >> 6;               // / FF
        int f0 = k & (FF - 1);
        float4 sv = ((const float4*)Sup)[e - NX4];
        float s0, c0, s1, c1, s2, c2, s3, c3;
        sincosf(sv.x, &s0, &c0);
        sincosf(sv.y, &s1, &c1);
        sincosf(sv.z, &s2, &c2);
        sincosf(sv.w, &s3, &c3);
        g_Sc[(f0 + 0) * SS + j] = c0;
        g_Sc[(f0 + 1) * SS + j] = c1;
        g_Sc[(f0 + 2) * SS + j] = c2;
        g_Sc[(f0 + 3) * SS + j] = c3;
        g_Ss[(f0 + 0) * SS + j] = s0;
        g_Ss[(f0 + 1) * SS + j] = s1;
        g_Ss[(f0 + 2) * SS + j] = s2;
        g_Ss[(f0 + 3) * SS + j] = s3;
    }
}

// ---------------------------------------------------------------------------
// Phase 2: main kernel. Single wave of 128 blocks. Per thread: 8 i x 4 j-pair
// register tile of running packed products; 3 f32x2 ops per (i, pair, f).
// Staging fully vectorized to float4 (LDG.128/STS.128).
// ---------------------------------------------------------------------------
__global__ __launch_bounds__(NTHREADS) void qk_kernel(const float* __restrict__ W) {
    extern __shared__ float smem_raw[];
    float2* xc = (float2*)smem_raw;            // [BI][FF] 32 KB (broadcast reads)
    float2* xs = xc + BI * FF;                 // [BI][FF] 32 KB
    float*  sc = (float*)(xs + BI * FF);       // [FF][BJ] 64 KB (pairwise LDS.64)
    float*  sn = sc + FF * BJ;                 // [FF][BJ] 64 KB
    float*  ws = sn + FF * BJ;                 // [BJ]      1 KB

    const int tid = threadIdx.x;
    const int i0  = blockIdx.x * BI;
    const int j0  = blockIdx.y * BJ;

    // --- Stage X splat tiles, float4 vectorized ---
    {
        const float4* src_c = (const float4*)(g_Xc + i0 * FF);   // 16B aligned
        const float4* src_s = (const float4*)(g_Xs + i0 * FF);
        float4* dst_c = (float4*)xc;
        float4* dst_s = (float4*)xs;
        #pragma unroll
        for (int e = tid; e < BI * FF / 2; e += NTHREADS) {      // 2048 float4s
            dst_c[e] = src_c[e];
            dst_s[e] = src_s[e];
        }
    }
    // --- Stage S planes [f][j_local], float4 vectorized ---
    {
        float4* dst_c = (float4*)sc;
        float4* dst_s = (float4*)sn;
        #pragma unroll
        for (int e = tid; e < FF * BJ / 4; e += NTHREADS) {      // 4096 float4s
            int f   = e >> 6;              // / (BJ/4)
            int jl4 = e & 63;
            const float4* row_c = (const float4*)(g_Sc + f * SS + j0);  // j0 mult of 256
            const float4* row_s = (const float4*)(g_Ss + f * SS + j0);
            dst_c[(f << 6) + jl4] = row_c[jl4];
            dst_s[(f << 6) + jl4] = row_s[jl4];
        }
    }
    ws[tid] = W[j0 + tid];          // NTHREADS == BJ
    __syncthreads();

    const int tx = tid & 31;    // j-pair lane
    const int ty = tid >> 5;    // warp id; i_local = ty + ii*8

    u64 p[TI][TJP];
    #pragma unroll
    for (int ii = 0; ii < TI; ii++)
        #pragma unroll
        for (int jp = 0; jp < TJP; jp++)
            p[ii][jp] = ONE2;

    #pragma unroll 1   // body ~1.8KB fits L0 I$; full unroll would thrash it
    for (int f = 0; f < FF; f++) {
        u64 bc[TJP], bs[TJP];
        #pragma unroll
        for (int jp = 0; jp < TJP; jp++) {
            int sj = f * BJ + 2 * (tx + jp * 32);
            bc[jp] = *(const u64*)&sc[sj];     // conflict-free LDS.64 (j-pair)
            bs[jp] = *(const u64*)&sn[sj];
        }
        #pragma unroll
        for (int ii = 0; ii < TI; ii++) {
            int xi = (ty + ii * 8) * FF + f;
            u64 axc = *(const u64*)&xc[xi];    // broadcast LDS.64, pre-splatted
            u64 axs = *(const u64*)&xs[xi];
            #pragma unroll
            for (int jp = 0; jp < TJP; jp++) {
                u64 t = fma2(axc, bc[jp], HALF2);
                t     = fma2(axs, bs[jp], t);
                p[ii][jp] = mul2(p[ii][jp], t);
            }
        }
    }

    // Weighted accumulate (packed), horizontal sum, warp-reduce over j-lanes.
    #pragma unroll
    for (int ii = 0; ii < TI; ii++) {
        u64 acc = 0ULL;  // packed (0,0)
        #pragma unroll
        for (int jp = 0; jp < TJP; jp++) {
            u64 w2 = *(const u64*)&ws[2 * (tx + jp * 32)];
            acc = fma2(p[ii][jp], w2, acc);
        }
        unsigned lo, hi;
        asm("mov.b64 {%0, %1}, %2;" : "=r"(lo), "=r"(hi) : "l"(acc));
        float v = __uint_as_float(lo) + __uint_as_float(hi);
        #pragma unroll
        for (int off = 16; off > 0; off >>= 1)
            v += __shfl_xor_sync(0xFFFFFFFFu, v, off);
        if (tx == 0)
            g_partial[blockIdx.y * BB + i0 + ty + ii * 8] = v;  // deterministic
    }
}

// ---------------------------------------------------------------------------
// Phase 3: reduce j-splits + bias, float4 over i.
// ---------------------------------------------------------------------------
__global__ void reduce_kernel(float* __restrict__ out, const float* __restrict__ b) {
    int i4 = blockIdx.x * blockDim.x + threadIdx.x;   // float4 index over i
    if (i4 < BB / 4) {
        float bias = b[0];
        float4 s = make_float4(bias, bias, bias, bias);
        #pragma unroll
        for (int y = 0; y < NSPLIT; y++) {
            float4 v = ((const float4*)(g_partial + y * BB))[i4];
            s.x += v.x; s.y += v.y; s.z += v.z; s.w += v.w;
        }
        ((float4*)out)[i4] = s;
    }
}

// ---------------------------------------------------------------------------
extern "C" void kernel_launch(void* const* d_in, const int* in_sizes, int n_in,
                              void* d_out, int out_size) {
    const float* X   = (const float*)d_in[0];   // [2048, 64]
    const float* Sup = (const float*)d_in[1];   // [1024, 64]
    const float* W   = (const float*)d_in[2];   // [1, 1024]
    const float* b   = (const float*)d_in[3];   // [1]
    float* out = (float*)d_out;                 // [2048]

    prep_kernel<<<(NX4 + NS4 + 255) / 256, 256>>>(X, Sup);

    size_t shmem = (size_t)(2 * BI * FF) * sizeof(float2)      // X splat tiles
                 + (size_t)(2 * FF * BJ + BJ) * sizeof(float); // S planes + W
    cudaFuncSetAttribute(qk_kernel, cudaFuncAttributeMaxDynamicSharedMemorySize, (int)shmem);
    qk_kernel<<<dim3(BB / BI, NSPLIT), NTHREADS, shmem>>>(W);

    reduce_kernel<<<(BB / 4 + 255) / 256, 256>>>(out, b);
}